// round 15
// baseline (speedup 1.0000x reference)
#include <cuda_runtime.h>
#include <math_constants.h>
#include <cstdint>

// SoftmaxTreeWithLoss on GB300 (sm_103a).
// x: [N=16, C=4096, H=26, W=26] f32; label: [N,26,26] i32 in [0,C)
// Tree: group 0 = channels [0,512) (roots); then 512 groups of 7 children.
// loss_pos = -( child-group logps + x[root] - LSE(root group) ).
//
// R14: every 128B-granule request pattern (LDG scalar/float2/cp.async 16B,
// bulk 128B, any MLP, any warp count) pins at 1.7-2.7TB/s. This round issues
// LARGE contiguous transfers: stream CTA = (image, 16-channel slab), 4 x
// cp.async.bulk of 10816B (4 contiguous channel rows each) into 43KB smem,
// per-position exp partials accumulated in registers, one spread atomicAdd
// per position into g_S. Chain CTAs (same grid, scheduled last) do the
// S-independent walk, spin on a done counter, then finish with log(g_S).

#define HW_SZ 676
#define ROOT_CH 512
#define CH_PER_SLAB 16
#define SLABS 32                       // 512 / 16
#define NCHUNK 4                       // 4 channels per bulk copy
#define CH_PER_CHUNK 4
#define CHUNK_BYTES (CH_PER_CHUNK * HW_SZ * 4)     // 10816
#define TILE_FLOATS (CH_PER_SLAB * HW_SZ)          // 10816
#define DSMEM_BYTES (TILE_FLOATS * 4)              // 43264
#define THREADS 256

#define MAX_M (16 * HW_SZ)
__device__ float g_S[MAX_M + 1];       // [M]: exp-sums, [MAX_M]: done counter

__device__ __forceinline__ uint32_t smem_u32(const void* p) {
    return (uint32_t)__cvta_generic_to_shared(p);
}

__global__ __launch_bounds__(THREADS, 5)
void tree_loss_kernel(const float* __restrict__ x,
                      const int*   __restrict__ label,
                      const int*   __restrict__ group_offsets,
                      const int*   __restrict__ group_sizes,
                      const int*   __restrict__ cid_groups,
                      const int*   __restrict__ parents,
                      float* __restrict__ out,
                      int M, int Cn, int nStream, float inv_norm)
{
    extern __shared__ float tile[];                 // [16 ch][676 pos]
    __shared__ __align__(8) unsigned long long mbar[NCHUNK];
    __shared__ float red[8];

    const int tid  = threadIdx.x;
    const int lane = tid & 31;
    const int w    = tid >> 5;

    if ((int)blockIdx.x < nStream) {
        // ============ stream CTA: (image n, 16-channel slab) ============
        const int n    = blockIdx.x >> 5;
        const int slab = blockIdx.x & 31;
        const int c0   = slab * CH_PER_SLAB;
        const float* src = x + ((size_t)n * Cn + c0) * HW_SZ;

        if (tid == 0) {
            #pragma unroll
            for (int k = 0; k < NCHUNK; k++)
                asm volatile("mbarrier.init.shared.b64 [%0], 1;"
                             :: "r"(smem_u32(&mbar[k])) : "memory");
            asm volatile("fence.proxy.async.shared::cta;" ::: "memory");
        }
        __syncthreads();

        if (tid == 0) {
            #pragma unroll
            for (int k = 0; k < NCHUNK; k++) {
                const uint32_t mb = smem_u32(&mbar[k]);
                asm volatile("mbarrier.arrive.expect_tx.shared.b64 _, [%0], %1;"
                             :: "r"(mb), "r"((uint32_t)CHUNK_BYTES) : "memory");
                asm volatile(
                    "cp.async.bulk.shared::cta.global.mbarrier::complete_tx::bytes"
                    " [%0], [%1], %2, [%3];"
                    :: "r"(smem_u32(tile) + k * (uint32_t)CHUNK_BYTES),
                       "l"(src + (size_t)k * CH_PER_CHUNK * HW_SZ),
                       "r"((uint32_t)CHUNK_BYTES), "r"(mb)
                    : "memory");
            }
        }

        // thread t owns positions t, t+256, t+512 (676 = 2*256 + 164)
        float acc0 = 0.f, acc1 = 0.f, acc2 = 0.f;
        const int p2ok = (tid < HW_SZ - 2 * THREADS);   // tid < 164

        #pragma unroll
        for (int k = 0; k < NCHUNK; k++) {
            // wait for chunk k
            const uint32_t mb = smem_u32(&mbar[k]);
            uint32_t done;
            do {
                asm volatile(
                    "{\n\t.reg .pred p;\n\t"
                    "mbarrier.try_wait.parity.acquire.cta.shared::cta.b64 p, [%1], 0, 0x989680;\n\t"
                    "selp.b32 %0, 1, 0, p;\n\t}"
                    : "=r"(done) : "r"(mb) : "memory");
            } while (!done);

            const float* cb = tile + k * CH_PER_CHUNK * HW_SZ;
            #pragma unroll
            for (int cc = 0; cc < CH_PER_CHUNK; cc++) {
                const float* row = cb + cc * HW_SZ;
                acc0 += __expf(row[tid]);
                acc1 += __expf(row[tid + THREADS]);
                if (p2ok) acc2 += __expf(row[tid + 2 * THREADS]);
            }
        }

        float* gs = g_S + n * HW_SZ;
        atomicAdd(&gs[tid],           acc0);
        atomicAdd(&gs[tid + THREADS], acc1);
        if (p2ok) atomicAdd(&gs[tid + 2 * THREADS], acc2);

        __threadfence();
        __syncthreads();
        if (tid == 0) atomicAdd(&g_S[MAX_M], 1.0f);
    } else {
        // ============ chain CTA: walk, spin, finish ============
        const int pos = ((int)blockIdx.x - nStream) * THREADS + tid;
        const bool valid = pos < M;
        const int n  = valid ? (pos / HW_SZ) : 0;
        const int hw = valid ? (pos - n * HW_SZ) : 0;
        const float* base = x + (size_t)n * ((size_t)Cn * HW_SZ) + hw;

        float child_lp   = 0.f;   // self-contained child-group log-probs
        float root_logit = 0.f;   // group-0 logits on the chain
        float root_cnt   = 0.f;   // # group-0 terms (each needs lse0)

        int cur = valid ? label[pos] : -1;
        #pragma unroll 1
        for (int d = 0; d < 8; d++) {          // MAX_DEPTH = 8
            if (!__ballot_sync(0xffffffffu, cur >= 0)) break;
            if (cur >= 0) {
                const int g = cid_groups[cur];
                if (g == 0) {
                    root_logit += base[cur * HW_SZ];
                    root_cnt   += 1.f;
                } else {
                    const int go = group_offsets[g];
                    const int gs = group_sizes[g];   // 7
                    float ss = 0.f, xv = 0.f;
                    for (int j = 0; j < gs; j++) {
                        const float v = base[(go + j) * HW_SZ];
                        ss += __expf(v);
                        if (go + j == cur) xv = v;
                    }
                    child_lp += xv - __logf(ss);
                }
                cur = parents[cur];
            }
        }

        // wait for all stream CTAs (they never wait on us)
        if (tid == 0) {
            while (*(volatile float*)&g_S[MAX_M] < (float)nStream)
                __nanosleep(200);
        }
        __syncthreads();
        __threadfence();

        float loss = 0.f;
        if (valid) {
            const float S = __ldcg(&g_S[pos]);
            loss = -(child_lp + root_logit - root_cnt * __logf(S));
        }

        #pragma unroll
        for (int o = 16; o; o >>= 1)
            loss += __shfl_xor_sync(0xffffffffu, loss, o);
        if (lane == 0) red[w] = loss;
        __syncthreads();
        if (w == 0) {
            float t = (lane < 8) ? red[lane] : 0.f;
            #pragma unroll
            for (int o = 4; o; o >>= 1) t += __shfl_xor_sync(0xffffffffu, t, o);
            if (lane == 0) atomicAdd(out, t * inv_norm);
        }
    }
}

extern "C" void kernel_launch(void* const* d_in, const int* in_sizes, int n_in,
                              void* d_out, int out_size)
{
    const float* x     = (const float*)d_in[0];
    const int* label   = (const int*)d_in[1];
    const int* g_off   = (const int*)d_in[2];
    const int* g_sz    = (const int*)d_in[3];
    const int* cid     = (const int*)d_in[4];
    const int* par     = (const int*)d_in[5];
    float* out         = (float*)d_out;

    const int M  = in_sizes[1];             // N*H*W
    const int N  = M / HW_SZ;               // batch size
    const int Cn = in_sizes[0] / M;         // 4096
    const float inv_norm = 1.0f / (float)N;

    static bool attr_done = false;
    if (!attr_done) {
        cudaFuncSetAttribute(tree_loss_kernel,
                             cudaFuncAttributeMaxDynamicSharedMemorySize,
                             DSMEM_BYTES);
        attr_done = true;
    }

    void* gS_addr = nullptr;
    cudaGetSymbolAddress(&gS_addr, g_S);
    cudaMemsetAsync(gS_addr, 0, (MAX_M + 1) * sizeof(float));
    cudaMemsetAsync(d_out, 0, sizeof(float));

    const int nStream     = N * SLABS;                     // 512
    const int chainBlocks = (M + THREADS - 1) / THREADS;   // 43
    tree_loss_kernel<<<nStream + chainBlocks, THREADS, DSMEM_BYTES>>>(
        x, label, g_off, g_sz, cid, par, out, M, Cn, nStream, inv_norm);
}

// round 16
// speedup vs baseline: 1.5534x; 1.5534x over previous
#include <cuda_runtime.h>
#include <math_constants.h>

// SoftmaxTreeWithLoss on GB300 (sm_103a).
// x: [N=16, C=4096, H=26, W=26] f32; label: [N,26,26] i32 in [0,C)
// Tree: group 0 = channels [0,512) (roots); then 512 groups of 7 children.
// loss_pos = -( child-group logps + x[root] - LSE(root group) ).
//
// R15: every request path (LDG/cp.async/TMA, any granule, any MLP, any warp
// count) pins at ~1.7-2.7TB/s -> shared chip-level concurrency cap; the
// traffic floor (~30MB / ~3TB/s ~ 9-10us) is where R6 already sits. So:
// keep the R6 champion skeleton (8 stream + 1 chain warp, 338 CTAs) and cut
// the stream-phase instruction/issue cost 4x with float4-over-positions
// loads (transposed lane map: 8 position-groups x 4 channel-subs per warp).

#define HW_SZ 676              // 26*26
#define CN 4096
#define POS_PER_BLOCK 32
#define NW_STREAM 8
#define CH_PER_WARP 64         // 512 / 8
#define THREADS 288            // 8 stream + 1 chain warp

__global__ __launch_bounds__(THREADS, 3)
void tree_loss_kernel(const float* __restrict__ x,
                      const int*   __restrict__ label,
                      const int*   __restrict__ group_offsets,
                      const int*   __restrict__ group_sizes,
                      const int*   __restrict__ cid_groups,
                      const int*   __restrict__ parents,
                      float* __restrict__ out,
                      int M, float inv_norm)
{
    __shared__ float sm_s[NW_STREAM][POS_PER_BLOCK];

    const int lane = threadIdx.x & 31;
    const int w    = threadIdx.x >> 5;

    if (w < NW_STREAM) {
        // ---- stream warp: 64 channels x 32 positions, float4 over positions.
        // lane = pg*4 + cs: pg = 4-position group (0..7), cs = channel sub (0..3).
        const int pg = lane >> 2;
        const int cs = lane & 3;
        int pos4 = blockIdx.x * POS_PER_BLOCK + 4 * pg;
        if (pos4 >= M) pos4 = 0;               // M % 4 == 0: group stays in-image
        const int n  = pos4 / HW_SZ;
        const int hw = pos4 - n * HW_SZ;       // multiple of 4 -> 16B aligned

        const int c0 = w * CH_PER_WARP + cs;
        const float4* p4 = (const float4*)(x + (size_t)n * (CN * HW_SZ)
                                             + (size_t)c0 * HW_SZ + hw);
        // channel stride in float4 units: HW_SZ/4 = 169; step 4 channels/iter
        float4 acc = make_float4(0.f, 0.f, 0.f, 0.f);
        #pragma unroll
        for (int i = 0; i < CH_PER_WARP / 4; i++) {
            const float4 v = p4[(size_t)i * (HW_SZ)];   // 4*169 = 676 float4s
            acc.x += __expf(v.x);
            acc.y += __expf(v.y);
            acc.z += __expf(v.z);
            acc.w += __expf(v.w);
        }

        // fold the 4 channel-sub lanes (cs) of each position group
        #pragma unroll
        for (int o = 1; o <= 2; o <<= 1) {
            acc.x += __shfl_xor_sync(0xffffffffu, acc.x, o);
            acc.y += __shfl_xor_sync(0xffffffffu, acc.y, o);
            acc.z += __shfl_xor_sync(0xffffffffu, acc.z, o);
            acc.w += __shfl_xor_sync(0xffffffffu, acc.w, o);
        }
        if (cs == 0) {
            sm_s[w][4 * pg + 0] = acc.x;
            sm_s[w][4 * pg + 1] = acc.y;
            sm_s[w][4 * pg + 2] = acc.z;
            sm_s[w][4 * pg + 3] = acc.w;
        }
        __syncthreads();
    } else {
        // ---- chain warp: parent-chain walk, overlapped with the streaming ----
        const int pos = blockIdx.x * POS_PER_BLOCK + lane;
        const bool valid = pos < M;
        const int n  = valid ? (pos / HW_SZ) : 0;
        const int hw = valid ? (pos - n * HW_SZ) : 0;
        const float* base = x + (size_t)n * (CN * HW_SZ) + hw;

        float child_lp   = 0.f;   // self-contained child-group log-probs
        float root_logit = 0.f;   // group-0 logits on the chain
        float root_cnt   = 0.f;   // # group-0 terms (each needs lse0)

        int cur = valid ? label[pos] : -1;
        #pragma unroll 1
        for (int d = 0; d < 8; d++) {            // MAX_DEPTH = 8
            if (!__ballot_sync(0xffffffffu, cur >= 0)) break;
            if (cur >= 0) {
                const int g = cid_groups[cur];
                if (g == 0) {
                    root_logit += base[cur * HW_SZ];
                    root_cnt   += 1.f;
                } else {
                    const int go = group_offsets[g];
                    const int gs = group_sizes[g];   // 7
                    float ss = 0.f, xv = 0.f;
                    for (int j = 0; j < gs; j++) {
                        const float v = base[(go + j) * HW_SZ];
                        ss += __expf(v);
                        if (go + j == cur) xv = v;
                    }
                    child_lp += xv - __logf(ss);
                }
                cur = parents[cur];
            }
        }

        __syncthreads();

        // merge the 8 streaming partials for this position
        float S = 0.f;
        #pragma unroll
        for (int q = 0; q < NW_STREAM; q++) S += sm_s[q][lane];

        float loss = 0.f;
        if (valid)
            loss = -(child_lp + root_logit - root_cnt * __logf(S));

        #pragma unroll
        for (int o = 16; o; o >>= 1)
            loss += __shfl_xor_sync(0xffffffffu, loss, o);
        if (lane == 0)
            atomicAdd(out, loss * inv_norm);
    }
}

extern "C" void kernel_launch(void* const* d_in, const int* in_sizes, int n_in,
                              void* d_out, int out_size)
{
    const float* x     = (const float*)d_in[0];
    const int* label   = (const int*)d_in[1];
    const int* g_off   = (const int*)d_in[2];
    const int* g_sz    = (const int*)d_in[3];
    const int* cid     = (const int*)d_in[4];
    const int* par     = (const int*)d_in[5];
    float* out         = (float*)d_out;

    const int M = in_sizes[1];          // N*H*W (label element count)
    const int N = M / HW_SZ;            // batch size for normalization
    const float inv_norm = 1.0f / (float)N;

    cudaMemsetAsync(d_out, 0, sizeof(float));

    const int blocks = (M + POS_PER_BLOCK - 1) / POS_PER_BLOCK;
    tree_loss_kernel<<<blocks, THREADS>>>(x, label, g_off, g_sz, cid, par,
                                          out, M, inv_norm);
}

// round 17
// speedup vs baseline: 1.6775x; 1.0799x over previous
#include <cuda_runtime.h>
#include <math_constants.h>

// SoftmaxTreeWithLoss on GB300 (sm_103a).
// x: [N=16, C=4096, H=26, W=26] f32; label: [N,26,26] i32 in [0,C)
// Tree: group 0 = channels [0,512) (roots); then 512 groups of 7 children.
// loss_pos = -( child-group logps + x[root] - LSE(root group) ).
//
// R16 = R6 champion skeleton (8 stream warps + 1 chain warp, 338 CTAs) plus:
//  (a) chain child-gather unrolled to 8 PREDICATED PARALLEL loads (the
//      runtime-bound loop serialized ~7 cold-DRAM latencies on the critical
//      path; now they overlap),
//  (b) no memset node: per-block partials + arrival counter, last block sums
//      and writes out directly (self-resetting, graph-safe),
//  (c) __ldcg on stream loads (read-once; keep L1 for gathers/tables).

#define HW_SZ 676              // 26*26
#define CN 4096
#define POS_PER_BLOCK 32
#define NW_STREAM 8
#define CH_PER_WARP 64         // 512 / 8
#define THREADS 288            // 8 stream + 1 chain warp
#define MAX_BLOCKS 512

__device__ float        g_part[MAX_BLOCKS];
__device__ unsigned int g_count;            // zero-init; self-resetting

__global__ __launch_bounds__(THREADS, 3)
void tree_loss_kernel(const float* __restrict__ x,
                      const int*   __restrict__ label,
                      const int*   __restrict__ group_offsets,
                      const int*   __restrict__ group_sizes,
                      const int*   __restrict__ cid_groups,
                      const int*   __restrict__ parents,
                      float* __restrict__ out,
                      int M, float inv_norm)
{
    __shared__ float sm_s[NW_STREAM][POS_PER_BLOCK];

    const int lane = threadIdx.x & 31;
    const int w    = threadIdx.x >> 5;
    const int pos  = blockIdx.x * POS_PER_BLOCK + lane;
    const bool valid = pos < M;

    const int n  = valid ? (pos / HW_SZ) : 0;
    const int hw = valid ? (pos - n * HW_SZ) : 0;
    const float* base = x + (size_t)n * (CN * HW_SZ) + hw;

    if (w < NW_STREAM) {
        // ---- streaming warp: direct exp-sum over 64 root channels ----
        const int c0 = w * CH_PER_WARP;
        float s = 0.f;
        if (valid) {
            const float* p = base + (size_t)c0 * HW_SZ;
            float a0 = 0.f, a1 = 0.f, a2 = 0.f, a3 = 0.f;
            #pragma unroll
            for (int j = 0; j < CH_PER_WARP; j += 4) {
                const float v0 = __ldcg(p + (j + 0) * HW_SZ);
                const float v1 = __ldcg(p + (j + 1) * HW_SZ);
                const float v2 = __ldcg(p + (j + 2) * HW_SZ);
                const float v3 = __ldcg(p + (j + 3) * HW_SZ);
                a0 += __expf(v0);
                a1 += __expf(v1);
                a2 += __expf(v2);
                a3 += __expf(v3);
            }
            s = (a0 + a1) + (a2 + a3);
        }
        sm_s[w][lane] = s;
        __syncthreads();
    } else {
        // ---- chain warp: parent-chain walk, overlapped with streaming ----
        float child_lp   = 0.f;   // self-contained child-group log-probs
        float root_logit = 0.f;   // group-0 logits on the chain
        float root_cnt   = 0.f;   // # group-0 terms (each needs lse0)

        int cur = valid ? label[pos] : -1;
        #pragma unroll 1
        for (int d = 0; d < 8; d++) {            // MAX_DEPTH = 8
            if (!__ballot_sync(0xffffffffu, cur >= 0)) break;
            if (cur >= 0) {
                const int g = cid_groups[cur];
                if (g == 0) {
                    root_logit += base[cur * HW_SZ];
                    root_cnt   += 1.f;
                } else {
                    const int go = group_offsets[g];
                    const int gs = group_sizes[g];     // 7 here, <=8 general
                    // 8 predicated PARALLEL gathers (independent -> 1 latency)
                    float vv[8];
                    #pragma unroll
                    for (int j = 0; j < 8; j++)
                        vv[j] = (j < gs) ? base[(go + j) * HW_SZ]
                                         : -CUDART_INF_F;
                    float ss = 0.f, xv = 0.f;
                    #pragma unroll
                    for (int j = 0; j < 8; j++) {
                        ss += __expf(vv[j]);           // exp(-inf) = 0
                        if (j < gs && go + j == cur) xv = vv[j];
                    }
                    child_lp += xv - __logf(ss);
                }
                cur = parents[cur];
            }
        }

        __syncthreads();

        // merge the 8 streaming partials for this position
        float S = 0.f;
        #pragma unroll
        for (int q = 0; q < NW_STREAM; q++) S += sm_s[q][lane];

        float loss = 0.f;
        if (valid)
            loss = -(child_lp + root_logit - root_cnt * __logf(S));

        // warp-sum over the 32 positions -> per-block partial
        #pragma unroll
        for (int o = 16; o; o >>= 1)
            loss += __shfl_xor_sync(0xffffffffu, loss, o);

        // last-block finalize: no memset node, no atomic on out
        unsigned int isLast = 0;
        if (lane == 0) {
            g_part[blockIdx.x] = loss * inv_norm;
            __threadfence();
            isLast = (atomicAdd(&g_count, 1u) == gridDim.x - 1) ? 1u : 0u;
        }
        isLast = __shfl_sync(0xffffffffu, isLast, 0);
        if (isLast) {
            __threadfence();
            float t = 0.f;
            for (int i = lane; i < (int)gridDim.x; i += 32)
                t += __ldcg(&g_part[i]);
            #pragma unroll
            for (int o = 16; o; o >>= 1)
                t += __shfl_xor_sync(0xffffffffu, t, o);
            if (lane == 0) {
                *out = t;
                g_count = 0;          // reset for next graph replay
            }
        }
    }
}

extern "C" void kernel_launch(void* const* d_in, const int* in_sizes, int n_in,
                              void* d_out, int out_size)
{
    const float* x     = (const float*)d_in[0];
    const int* label   = (const int*)d_in[1];
    const int* g_off   = (const int*)d_in[2];
    const int* g_sz    = (const int*)d_in[3];
    const int* cid     = (const int*)d_in[4];
    const int* par     = (const int*)d_in[5];
    float* out         = (float*)d_out;

    const int M = in_sizes[1];          // N*H*W (label element count)
    const int N = M / HW_SZ;            // batch size for normalization
    const float inv_norm = 1.0f / (float)N;

    const int blocks = (M + POS_PER_BLOCK - 1) / POS_PER_BLOCK;   // 338
    tree_loss_kernel<<<blocks, THREADS>>>(x, label, g_off, g_sz, cid, par,
                                          out, M, inv_norm);
}